// round 17
// baseline (speedup 1.0000x reference)
#include <cuda_runtime.h>

// ---------------- problem constants ----------------
#define Bn 4
#define Ln 1024
#define Dn 1024
#define Hn 16
#define HDn 64
#define Fn 4096
#define Tn (Bn*Ln)              // 4096 tokens
#define SEG (Bn*Hn*Ln*HDn)      // 4,194,304 = one of Q/K/V in [B,H,L,HD]

// ---------------- scratch (device globals; no allocation) ----------------
__device__ float g_qkv[3u * SEG];          // Q,K,V each [B,H,L,HD] (pre-rounded)
__device__ float g_ctx[(size_t)Tn * Dn];   // ctx in [B,L,D] (pre-rounded)
__device__ float g_attnout[(size_t)Tn * Dn];
__device__ float g_y1[(size_t)Tn * Dn];    // exact (residual use)
__device__ float g_y1r[(size_t)Tn * Dn];   // pre-rounded (FF1 A operand)
__device__ float g_h1[(size_t)Tn * Fn];    // relu(ff1), pre-rounded
__device__ float g_f2[(size_t)Tn * Dn];
__device__ float g_wr_in[3u * Dn * Dn];    // rounded in_proj_w
__device__ float g_wr_out[(size_t)Dn * Dn];
__device__ float g_wr1[(size_t)Fn * Dn];
__device__ float g_wr2[(size_t)Dn * Fn];
__device__ float g_xr[(size_t)Tn * Dn];    // rounded x

// ---------------- helpers ----------------
__device__ __forceinline__ void cp16(void* s, const void* g) {
    unsigned sa = (unsigned)__cvta_generic_to_shared(s);
    asm volatile("cp.async.cg.shared.global [%0], [%1], 16;" :: "r"(sa), "l"(g));
}
#define CP_COMMIT() asm volatile("cp.async.commit_group;" ::: "memory")
#define CP_WAIT(n)  asm volatile("cp.async.wait_group %0;" :: "n"(n) : "memory")

// round-to-nearest(ties-away) tf32 lives in MEMORY now: bits+0x1000, HMMA
// truncates low 13 bits at consumption -> identical to cvt.rna at frag time.
__device__ __forceinline__ float rndf(float f) {
    return __uint_as_float(__float_as_uint(f) + 0x1000u);
}

__device__ __forceinline__ void mma_tf32(float* c, const unsigned* a, const unsigned* b) {
    asm volatile(
        "mma.sync.aligned.m16n8k8.row.col.f32.tf32.tf32.f32 "
        "{%0,%1,%2,%3}, {%4,%5,%6,%7}, {%8,%9}, {%0,%1,%2,%3};"
        : "+f"(c[0]), "+f"(c[1]), "+f"(c[2]), "+f"(c[3])
        : "r"(a[0]), "r"(a[1]), "r"(a[2]), "r"(a[3]), "r"(b[0]), "r"(b[1]));
}

// ---------------- operand pre-rounding (weights + x), one launch -----------
// grid (4096, 5); each thread one float4 of one segment.
__global__ __launch_bounds__(256)
void round_all(const float* __restrict__ w_in, const float* __restrict__ w_out,
               const float* __restrict__ w1,   const float* __restrict__ w2,
               const float* __restrict__ x,
               float* __restrict__ o0, float* __restrict__ o1,
               float* __restrict__ o2, float* __restrict__ o3,
               float* __restrict__ o4)
{
    const int seg = blockIdx.y;
    const long i = (long)blockIdx.x * 256 + threadIdx.x;   // float4 index
    const float* src; float* dst; long n4;
    if      (seg == 0) { src = w_in;  dst = o0; n4 = (long)3*Dn*Dn/4; }
    else if (seg == 1) { src = w_out; dst = o1; n4 = (long)Dn*Dn/4; }
    else if (seg == 2) { src = w1;    dst = o2; n4 = (long)Fn*Dn/4; }
    else if (seg == 3) { src = w2;    dst = o3; n4 = (long)Dn*Fn/4; }
    else               { src = x;     dst = o4; n4 = (long)Tn*Dn/4; }
    if (i < n4) {
        uint4 v = ((const uint4*)src)[i];
        v.x += 0x1000u; v.y += 0x1000u; v.z += 0x1000u; v.w += 0x1000u;
        ((uint4*)dst)[i] = v;
    }
}

// ---------------- TF32 GEMM: cp.async 5-stage pipeline, 256x128 tile ----------
// C = A(MxK) @ B^T, operands PRE-ROUNDED in memory. B is [N,K] row-major.
// EPI: 0 bias(exact) | 1 bias+relu(store rounded) | 2 bias+QKV scatter(rounded)
#define TG_STG 5
#define TG_BM 256
#define TG_BN 128
#define TG_SMEM (TG_STG * (TG_BM*20 + TG_BN*20) * 4)   // 153600 bytes

template<int EPI>
__global__ __launch_bounds__(256, 1)
void tgemm(const float* __restrict__ A, const float* __restrict__ Bm,
           const float* __restrict__ bias, float* __restrict__ C,
           int M, int N, int K, int lda, int ldb, int ldc)
{
    constexpr int BM = TG_BM, BN = TG_BN;
    constexpr int BK = 16;
    constexpr int KP = 20;              // pad: conflict-free fragment LDS
    constexpr int NA = BM / 64;
    constexpr int NB = BN / 64;

    extern __shared__ unsigned dsm[];
    unsigned* AsB = dsm;                         // [STG][BM][KP]
    unsigned* BsB = dsm + TG_STG * BM * KP;      // [STG][BN][KP]

    const int tid  = threadIdx.x;
    const int warp = tid >> 5, lane = tid & 31;
    const int wm = (warp >> 1) * 64;             // warp tile: 64 x 64
    const int wn = (warp & 1) * 64;
    const int m0 = blockIdx.y * BM;
    const int n0 = blockIdx.x * BN;
    const int lr = lane >> 2, lc = lane & 3;
    const int ar = tid >> 2, ac4 = (tid & 3) * 4;

    float acc[4][8][4];
#pragma unroll
    for (int i = 0; i < 4; i++)
#pragma unroll
        for (int j = 0; j < 8; j++)
#pragma unroll
            for (int e = 0; e < 4; e++) acc[i][j][e] = 0.0f;

    auto issue = [&](int k0, int st) {
        unsigned* As = AsB + st * BM * KP;
        unsigned* Bs = BsB + st * BN * KP;
#pragma unroll
        for (int i = 0; i < NA; i++) {
            int r = ar + i * 64;
            cp16(As + r * KP + ac4, A + (long)(m0 + r) * lda + k0 + ac4);
        }
#pragma unroll
        for (int i = 0; i < NB; i++) {
            int r = ar + i * 64;
            cp16(Bs + r * KP + ac4, Bm + (long)(n0 + r) * ldb + k0 + ac4);
        }
    };

    const int NIT = K / BK;
    int fetch = 0;
#pragma unroll
    for (int p = 0; p < TG_STG - 1; p++) {
        if (fetch < NIT) issue(fetch * BK, fetch % TG_STG);
        CP_COMMIT();
        fetch++;
    }

    for (int it = 0; it < NIT; it++) {
        CP_WAIT(TG_STG - 2);
        __syncthreads();
        if (fetch < NIT) issue(fetch * BK, fetch % TG_STG);
        CP_COMMIT();
        fetch++;

        const unsigned* Ac = AsB + (it % TG_STG) * BM * KP;
        const unsigned* Bc = BsB + (it % TG_STG) * BN * KP;

#pragma unroll
        for (int ks = 0; ks < 2; ks++) {
            const int kb = ks * 8;
            unsigned af[4][4];
#pragma unroll
            for (int mt = 0; mt < 4; mt++) {
                const int rbase = wm + mt * 16 + lr;
                af[mt][0] = Ac[(rbase    ) * KP + kb + lc    ];
                af[mt][1] = Ac[(rbase + 8) * KP + kb + lc    ];
                af[mt][2] = Ac[(rbase    ) * KP + kb + lc + 4];
                af[mt][3] = Ac[(rbase + 8) * KP + kb + lc + 4];
            }
            unsigned bf[8][2];
#pragma unroll
            for (int nt = 0; nt < 8; nt++) {
                const int nb = wn + nt * 8 + lr;
                bf[nt][0] = Bc[nb * KP + kb + lc    ];
                bf[nt][1] = Bc[nb * KP + kb + lc + 4];
            }
#pragma unroll
            for (int mt = 0; mt < 4; mt++)
#pragma unroll
                for (int nt = 0; nt < 8; nt++)
                    mma_tf32(acc[mt][nt], af[mt], bf[nt]);
        }
    }

    // ---------------- epilogue ----------------
#pragma unroll
    for (int mt = 0; mt < 4; mt++) {
#pragma unroll
        for (int nt = 0; nt < 8; nt++) {
            const int gn = n0 + wn + nt * 8 + 2 * lc;
#pragma unroll
            for (int h = 0; h < 2; h++) {
                const int m = m0 + wm + mt * 16 + lr + h * 8;
                float v0 = acc[mt][nt][h * 2 + 0] + bias[gn];
                float v1 = acc[mt][nt][h * 2 + 1] + bias[gn + 1];
                if (EPI == 0) {
                    *(float2*)(C + (long)m * ldc + gn) = make_float2(v0, v1);
                } else if (EPI == 1) {   // relu, store pre-rounded for FF2
                    v0 = rndf(fmaxf(v0, 0.0f)); v1 = rndf(fmaxf(v1, 0.0f));
                    *(float2*)(C + (long)m * ldc + gn) = make_float2(v0, v1);
                } else {                 // EPI == 2: QKV scatter, pre-rounded
                    v0 = rndf(v0); v1 = rndf(v1);
                    const int part = gn >> 10;
                    const int d = gn & 1023;
                    const int hh = d >> 6, hd = d & 63;
                    const int b = m >> 10, l = m & 1023;
                    float* p = C + (long)part * SEG
                             + (((long)(b * Hn + hh) * Ln + l) * HDn + hd);
                    *(float2*)p = make_float2(v0, v1);
                }
            }
        }
    }
}

// ---------------- fused attention: S=QK^T+mask -> softmax -> attn_w + P@V ----
// One block: 32 query rows of one (b,h). 256 threads. Q/K/V pre-rounded.
// smem (words): Qs[32][68] | Ks[2][128][68] | Ss[32][1028]; Vs aliases Ks.
#define ATT_SMEM_WORDS (32*68 + 2*128*68 + 32*1028)
#define ATT_SMEM_BYTES (ATT_SMEM_WORDS * 4)

__global__ __launch_bounds__(256)
void attn_fused(const float* __restrict__ Q, const float* __restrict__ Kg,
                const float* __restrict__ Vg, const float* __restrict__ mask,
                float* __restrict__ attnw, float* __restrict__ ctx)
{
    extern __shared__ unsigned sm[];
    unsigned* Qs = sm;                     // [32][68]
    unsigned* Ks = Qs + 32 * 68;           // [2][128][68] double buffer
    unsigned* Ss = Ks + 2 * 128 * 68;      // [32][1028]  fp32 S, later rounded P
    unsigned* Vs = Ks;                     // [64][132] V^T tile (aliases Ks)

    const int tid  = threadIdx.x;
    const int warp = tid >> 5, lane = tid & 31;
    const int lr = lane >> 2, lc = lane & 3;
    const int z  = blockIdx.x >> 5;        // batch-head 0..63
    const int rb = blockIdx.x & 31;        // 32-row block 0..31
    const int row0 = rb * 32;
    const long zoff = (long)z * Ln * HDn;

    // ---- async load Q tile 32x64 ----
#pragma unroll
    for (int i = 0; i < 2; i++) {
        int idx = tid + i * 256;
        int r = idx >> 4, c4 = (idx & 15) * 4;
        cp16(&Qs[r * 68 + c4], Q + zoff + (long)(row0 + r) * HDn + c4);
    }
    CP_COMMIT();

    auto issueK = [&](int kt, int st) {
        unsigned* Kb = Ks + st * (128 * 68);
#pragma unroll
        for (int i = 0; i < 8; i++) {      // K tile 128x64
            int idx = tid + i * 256;
            int r = idx >> 4, c4 = (idx & 15) * 4;
            cp16(&Kb[r * 68 + c4], Kg + zoff + (long)(kt * 128 + r) * HDn + c4);
        }
    };

    // ---- phase 1: S = Q@K^T * 0.125 + mask  (fp32 into Ss) ----
    const int wmS = (warp & 1) * 16;       // 2 x 4 warps over 32 x 128
    const int wnS = (warp >> 1) * 32;

    issueK(0, 0); CP_COMMIT();
    for (int kt = 0; kt < 8; kt++) {
        if (kt + 1 < 8) { issueK(kt + 1, (kt + 1) & 1); CP_COMMIT(); CP_WAIT(1); }
        else            { CP_WAIT(0); }
        __syncthreads();
        const unsigned* Kc = Ks + (kt & 1) * (128 * 68);

        float acc[4][4];
#pragma unroll
        for (int nt = 0; nt < 4; nt++)
#pragma unroll
            for (int e = 0; e < 4; e++) acc[nt][e] = 0.0f;

#pragma unroll
        for (int ks = 0; ks < 8; ks++) {
            const int kb = ks * 8;
            unsigned af[4];
            af[0] = Qs[(wmS + lr    ) * 68 + kb + lc    ];
            af[1] = Qs[(wmS + lr + 8) * 68 + kb + lc    ];
            af[2] = Qs[(wmS + lr    ) * 68 + kb + lc + 4];
            af[3] = Qs[(wmS + lr + 8) * 68 + kb + lc + 4];
#pragma unroll
            for (int nt = 0; nt < 4; nt++) {
                unsigned bf[2];
                const int nb = wnS + nt * 8 + lr;
                bf[0] = Kc[nb * 68 + kb + lc    ];
                bf[1] = Kc[nb * 68 + kb + lc + 4];
                mma_tf32(acc[nt], af, bf);
            }
        }

        // epilogue: scale + mask -> Ss (fp32, exact)
#pragma unroll
        for (int nt = 0; nt < 4; nt++) {
            const int col = kt * 128 + wnS + nt * 8 + 2 * lc;
#pragma unroll
            for (int h = 0; h < 2; h++) {
                const int r  = wmS + lr + h * 8;               // local row
                const int gm = row0 + r;                       // global L row
                float2 mk = *(const float2*)(mask + (long)gm * Ln + col);
                float s0 = acc[nt][h * 2 + 0] * 0.125f + mk.x;
                float s1 = acc[nt][h * 2 + 1] * 0.125f + mk.y;
                *(float2*)&Ss[r * 1028 + col] = make_float2(s0, s1);
            }
        }
        __syncthreads();   // all reads of Kc done before buffer reuse
    }

    // ---- phase 2: softmax; exact attn_w to global; rounded P into Ss ----
    {
#pragma unroll
        for (int j = 0; j < 4; j++) {
            const int r = warp * 4 + j;
            float4 v[8];
#pragma unroll
            for (int i = 0; i < 8; i++)
                v[i] = *(float4*)&Ss[r * 1028 + lane * 4 + i * 128];
            float mx = -3.4e38f;
#pragma unroll
            for (int i = 0; i < 8; i++)
                mx = fmaxf(mx, fmaxf(fmaxf(v[i].x, v[i].y), fmaxf(v[i].z, v[i].w)));
#pragma unroll
            for (int s = 16; s > 0; s >>= 1)
                mx = fmaxf(mx, __shfl_xor_sync(0xffffffffu, mx, s));
            float sum = 0.0f;
#pragma unroll
            for (int i = 0; i < 8; i++) {
                v[i].x = __expf(v[i].x - mx); v[i].y = __expf(v[i].y - mx);
                v[i].z = __expf(v[i].z - mx); v[i].w = __expf(v[i].w - mx);
                sum += v[i].x + v[i].y + v[i].z + v[i].w;
            }
#pragma unroll
            for (int s = 16; s > 0; s >>= 1)
                sum += __shfl_xor_sync(0xffffffffu, sum, s);
            const float inv = 1.0f / sum;
            float* aw = attnw + (long)z * Ln * Ln + (long)(row0 + r) * Ln;
#pragma unroll
            for (int i = 0; i < 8; i++) {
                v[i].x *= inv; v[i].y *= inv; v[i].z *= inv; v[i].w *= inv;
                *(float4*)(aw + lane * 4 + i * 128) = v[i];
                unsigned* p = &Ss[r * 1028 + lane * 4 + i * 128];
                p[0] = __float_as_uint(v[i].x) + 0x1000u;
                p[1] = __float_as_uint(v[i].y) + 0x1000u;
                p[2] = __float_as_uint(v[i].z) + 0x1000u;
                p[3] = __float_as_uint(v[i].w) + 0x1000u;
            }
        }
    }

    // ---- phase 3: O = P @ V (register-prefetched V tiles) ----
    const int wmO = (warp & 1) * 16;       // 2 x 4 warps over 32 x 64
    const int wnO = (warp >> 1) * 16;
    float acco[2][4];
#pragma unroll
    for (int nt = 0; nt < 2; nt++)
#pragma unroll
        for (int e = 0; e < 4; e++) acco[nt][e] = 0.0f;

    float2 vreg[16];
    auto ldV = [&](int vt) {
#pragma unroll
        for (int i = 0; i < 16; i++) {
            int p = warp + i * 8;          // 0..127 patches of 4(r) x 16(n)
            int r = (p & 31) * 4 + (lane >> 3);
            int n = (p >> 5) * 16 + (lane & 7) * 2;
            vreg[i] = *(const float2*)(Vg + zoff + (long)(vt * 128 + r) * HDn + n);
        }
    };
    auto stV = [&]() {
#pragma unroll
        for (int i = 0; i < 16; i++) {
            int p = warp + i * 8;
            int r = (p & 31) * 4 + (lane >> 3);
            int n = (p >> 5) * 16 + (lane & 7) * 2;
            Vs[(n    ) * 132 + r] = __float_as_uint(vreg[i].x);
            Vs[(n + 1) * 132 + r] = __float_as_uint(vreg[i].y);
        }
    };

    ldV(0);
    for (int vt = 0; vt < 8; vt++) {
        __syncthreads();                   // prev Vs readers done; P ready (vt==0)
        stV();
        if (vt + 1 < 8) ldV(vt + 1);       // LDG overlapped with compute below
        __syncthreads();

#pragma unroll
        for (int ks = 0; ks < 16; ks++) {
            const int kk = vt * 128 + ks * 8;
            unsigned af[4];
            af[0] = Ss[(wmO + lr    ) * 1028 + kk + lc    ];
            af[1] = Ss[(wmO + lr + 8) * 1028 + kk + lc    ];
            af[2] = Ss[(wmO + lr    ) * 1028 + kk + lc + 4];
            af[3] = Ss[(wmO + lr + 8) * 1028 + kk + lc + 4];
#pragma unroll
            for (int nt = 0; nt < 2; nt++) {
                unsigned bf[2];
                const int nb = wnO + nt * 8 + lr;
                bf[0] = Vs[nb * 132 + ks * 8 + lc    ];
                bf[1] = Vs[nb * 132 + ks * 8 + lc + 4];
                mma_tf32(acco[nt], af, bf);
            }
        }
    }

    // ---- write O (pre-rounded: feeds out-proj GEMM only) ----
    const int b = z >> 4, hh = z & 15;
#pragma unroll
    for (int nt = 0; nt < 2; nt++) {
        const int hd = wnO + nt * 8 + 2 * lc;
#pragma unroll
        for (int h = 0; h < 2; h++) {
            const int m = row0 + wmO + lr + h * 8;
            float* p = ctx + (((long)(b * Ln + m) * Hn + hh) * HDn + hd);
            *(float2*)p = make_float2(rndf(acco[nt][h * 2]), rndf(acco[nt][h * 2 + 1]));
        }
    }
}

// ---------------- fused residual add + LayerNorm ----------------
// DUAL=1: also write pre-rounded copy (GEMM A operand) to outr.
template<int DUAL>
__global__ __launch_bounds__(256) void add_ln_kernel(
    const float* __restrict__ a, const float* __restrict__ b,
    const float* __restrict__ g, const float* __restrict__ beta,
    float* __restrict__ out, float* __restrict__ outr)
{
    __shared__ float r1[256];
    __shared__ float r2[256];
    const int tid = threadIdx.x;
    const long off = (long)blockIdx.x * 1024;

    float4 va = ((const float4*)(a + off))[tid];
    float4 vb = ((const float4*)(b + off))[tid];
    float4 s;
    s.x = va.x + vb.x; s.y = va.y + vb.y; s.z = va.z + vb.z; s.w = va.w + vb.w;

    float sum = s.x + s.y + s.z + s.w;
    float sq  = s.x*s.x + s.y*s.y + s.z*s.z + s.w*s.w;
    r1[tid] = sum; r2[tid] = sq; __syncthreads();
    for (int t = 128; t > 0; t >>= 1) {
        if (tid < t) { r1[tid] += r1[tid + t]; r2[tid] += r2[tid + t]; }
        __syncthreads();
    }
    const float mu   = r1[0] * (1.0f / 1024.0f);
    const float var  = r2[0] * (1.0f / 1024.0f) - mu * mu;
    const float rstd = rsqrtf(var + 1e-5f);

    float4 gv = ((const float4*)g)[tid];
    float4 bv = ((const float4*)beta)[tid];
    float4 o;
    o.x = (s.x - mu) * rstd * gv.x + bv.x;
    o.y = (s.y - mu) * rstd * gv.y + bv.y;
    o.z = (s.z - mu) * rstd * gv.z + bv.z;
    o.w = (s.w - mu) * rstd * gv.w + bv.w;
    ((float4*)(out + off))[tid] = o;
    if (DUAL) {
        float4 orr;
        orr.x = rndf(o.x); orr.y = rndf(o.y); orr.z = rndf(o.z); orr.w = rndf(o.w);
        ((float4*)(outr + off))[tid] = orr;
    }
}

// ---------------- launch ----------------
extern "C" void kernel_launch(void* const* d_in, const int* in_sizes, int n_in,
                              void* d_out, int out_size)
{
    (void)in_sizes; (void)n_in; (void)out_size;

    const float* x     = (const float*)d_in[0];
    const float* mask  = (const float*)d_in[1];
    const float* w_in  = (const float*)d_in[2];
    const float* b_in  = (const float*)d_in[3];
    const float* w_out = (const float*)d_in[4];
    const float* b_out = (const float*)d_in[5];
    const float* w1    = (const float*)d_in[6];
    const float* b1    = (const float*)d_in[7];
    const float* w2    = (const float*)d_in[8];
    const float* b2    = (const float*)d_in[9];
    const float* g1    = (const float*)d_in[10];
    const float* be1   = (const float*)d_in[11];
    const float* g2    = (const float*)d_in[12];
    const float* be2   = (const float*)d_in[13];

    float* out_x    = (float*)d_out;                       // [B,L,D]
    float* out_attn = out_x + (size_t)Tn * Dn;             // [B,H,L,L]

    float *p_qkv, *p_ctx, *p_attnout, *p_y1, *p_y1r, *p_h1, *p_f2;
    float *p_wr_in, *p_wr_out, *p_wr1, *p_wr2, *p_xr;
    cudaGetSymbolAddress((void**)&p_qkv,     g_qkv);
    cudaGetSymbolAddress((void**)&p_ctx,     g_ctx);
    cudaGetSymbolAddress((void**)&p_attnout, g_attnout);
    cudaGetSymbolAddress((void**)&p_y1,      g_y1);
    cudaGetSymbolAddress((void**)&p_y1r,     g_y1r);
    cudaGetSymbolAddress((void**)&p_h1,      g_h1);
    cudaGetSymbolAddress((void**)&p_f2,      g_f2);
    cudaGetSymbolAddress((void**)&p_wr_in,   g_wr_in);
    cudaGetSymbolAddress((void**)&p_wr_out,  g_wr_out);
    cudaGetSymbolAddress((void**)&p_wr1,     g_wr1);
    cudaGetSymbolAddress((void**)&p_wr2,     g_wr2);
    cudaGetSymbolAddress((void**)&p_xr,      g_xr);

    const float* Q = p_qkv;
    const float* K = p_qkv + (size_t)SEG;
    const float* V = p_qkv + 2 * (size_t)SEG;

    static int attr_set = 0;
    if (!attr_set) {
        cudaFuncSetAttribute(attn_fused,
                             cudaFuncAttributeMaxDynamicSharedMemorySize,
                             ATT_SMEM_BYTES);
        cudaFuncSetAttribute(tgemm<0>,
                             cudaFuncAttributeMaxDynamicSharedMemorySize, TG_SMEM);
        cudaFuncSetAttribute(tgemm<1>,
                             cudaFuncAttributeMaxDynamicSharedMemorySize, TG_SMEM);
        cudaFuncSetAttribute(tgemm<2>,
                             cudaFuncAttributeMaxDynamicSharedMemorySize, TG_SMEM);
        attr_set = 1;
    }

    // 0) pre-round weights + x (launch index 0)
    round_all<<<dim3(4096, 5), 256>>>(w_in, w_out, w1, w2, x,
                                      p_wr_in, p_wr_out, p_wr1, p_wr2, p_xr);

    // 1) QKV = xr @ wr_in^T + b, scattered pre-rounded to [B,H,L,HD] x3
    tgemm<2><<<dim3(3072/TG_BN, Tn/TG_BM), 256, TG_SMEM>>>(
        p_xr, p_wr_in, b_in, p_qkv, Tn, 3*Dn, Dn, Dn, Dn, 0);

    // 2) fused attention: exact attn_w (d_out), pre-rounded ctx
    attn_fused<<<64 * 32, 256, ATT_SMEM_BYTES>>>(Q, K, V, mask, out_attn, p_ctx);

    // 3) attn_out = ctx @ wr_out^T + b   <- ncu capture slot (index 3)
    tgemm<0><<<dim3(Dn/TG_BN, Tn/TG_BM), 256, TG_SMEM>>>(
        p_ctx, p_wr_out, b_out, p_attnout, Tn, Dn, Dn, Dn, Dn, Dn);

    // 4) y1 = LN(x + attn_out), exact + rounded copy
    add_ln_kernel<1><<<Tn, 256>>>(x, p_attnout, g1, be1, p_y1, p_y1r);

    // 5) h1 = relu(y1r @ wr1^T + b1), stored pre-rounded
    tgemm<1><<<dim3(Fn/TG_BN, Tn/TG_BM), 256, TG_SMEM>>>(
        p_y1r, p_wr1, b1, p_h1, Tn, Fn, Dn, Dn, Dn, Fn);

    // 6) f2 = h1 @ wr2^T + b2 (exact)
    tgemm<0><<<dim3(Dn/TG_BN, Tn/TG_BM), 256, TG_SMEM>>>(
        p_h1, p_wr2, b2, p_f2, Tn, Dn, Fn, Fn, Fn, Dn);

    // 7) out_x = LN(y1 + f2)
    add_ln_kernel<0><<<Tn, 256>>>(p_y1, p_f2, g2, be2, out_x, nullptr);
}